// round 3
// baseline (speedup 1.0000x reference)
#include <cuda_runtime.h>

typedef unsigned long long u64;

#define IN_H 4096
#define IN_W 4096
#define KH 16
#define KW 16
#define OUT_H 4081
#define OUT_W 4081

#define TILE_ROWS 64       // output rows per block
#define TILE_COLS 128      // output cols per block
#define PITCH 148          // smem input pitch (floats): mult of 4, 148%16=4 -> 2-way on row loads
#define TPITCH 129         // smem transpose pitch (floats): 2*129 % 32 = 2 -> 2-way STS
#define SX_ROWS (TILE_ROWS + KH - 1)   // 79
#define SX_C4 36           // float4 per smem row (144 floats >= 143 needed)

// ---- packed fp32x2 helpers ----
__device__ __forceinline__ u64 ffma2(u64 a, u64 b, u64 c) {
    u64 d;
    asm("fma.rn.f32x2 %0, %1, %2, %3;" : "=l"(d) : "l"(a), "l"(b), "l"(c));
    return d;
}
__device__ __forceinline__ u64 pack2(float lo, float hi) {
    return (u64)__float_as_uint(lo) | ((u64)__float_as_uint(hi) << 32);
}
__device__ __forceinline__ u64 shift_in(u64 v, float nv) {
    // new pair = (old.hi, nv)
    return (v >> 32) | ((u64)__float_as_uint(nv) << 32);
}
__device__ __forceinline__ float f2_lo(u64 v) { return __uint_as_float((unsigned)(v & 0xffffffffull)); }
__device__ __forceinline__ float f2_hi(u64 v) { return __uint_as_float((unsigned)(v >> 32)); }

__global__ __launch_bounds__(256, 2)
void conv2d_f32x2_kernel(const float* __restrict__ x,
                         const float* __restrict__ w,
                         const float* __restrict__ bias,
                         float* __restrict__ out)
{
    __shared__ float sx[SX_ROWS * PITCH];   // 46.8 KB, reused as transpose buffer
    __shared__ float sw[KH * KW];

    const int tid  = threadIdx.x;
    const int col0 = blockIdx.x * TILE_COLS;
    const int row0 = blockIdx.y * TILE_ROWS;

    // ---- load weights (256 floats) ----
    sw[tid] = w[tid];

    // ---- stage input tile: 79 rows x 143 cols (pitch 148), zero-padded OOB ----
    for (int idx = tid; idx < SX_ROWS * SX_C4; idx += 256) {
        const int r  = idx / SX_C4;
        const int c4 = idx - r * SX_C4;
        const int gr = row0 + r;
        const int gc = col0 + c4 * 4;
        float4 v = make_float4(0.f, 0.f, 0.f, 0.f);
        if (gr < IN_H) {
            if (gc + 3 < IN_W) {
                v = *reinterpret_cast<const float4*>(x + (size_t)gr * IN_W + gc);
            } else {
                float t[4] = {0.f, 0.f, 0.f, 0.f};
                #pragma unroll
                for (int k = 0; k < 4; ++k)
                    if (gc + k < IN_W) t[k] = x[(size_t)gr * IN_W + gc + k];
                v = make_float4(t[0], t[1], t[2], t[3]);
            }
        }
        *reinterpret_cast<float4*>(sx + r * PITCH + c4 * 4) = v;
    }
    __syncthreads();

    // ---- mapping: lane -> output row pair, warp -> 16-col group ----
    const int lane = tid & 31;     // 0..31 -> row group
    const int wid  = tid >> 5;     // 0..7  -> col group
    const int orow = lane * 2;     // tile-local output row base (pair)
    const int ocol = wid * 16;     // tile-local output col base

    u64 acc[16];
    #pragma unroll
    for (int i = 0; i < 16; ++i) acc[i] = 0ull;

    // rolling vertical-pair buffer: vb[c] = (x[row+p][ocol+c], x[row+p+1][ocol+c])
    u64 vb[32];
    {
        const float* r0 = sx + orow * PITCH + ocol;
        #pragma unroll
        for (int c = 0; c < 32; c += 4) {
            float4 a = *reinterpret_cast<const float4*>(r0 + c);
            float4 b = *reinterpret_cast<const float4*>(r0 + PITCH + c);
            vb[c+0] = pack2(a.x, b.x);
            vb[c+1] = pack2(a.y, b.y);
            vb[c+2] = pack2(a.z, b.z);
            vb[c+3] = pack2(a.w, b.w);
        }
    }

    #pragma unroll 2
    for (int p = 0; p < KH; ++p) {
        const float* swr = sw + p * KW;
        #pragma unroll
        for (int q = 0; q < KW; ++q) {
            const float wv = swr[q];       // broadcast LDS (conflict-free)
            const u64 w2 = pack2(wv, wv);
            #pragma unroll
            for (int c = 0; c < 16; ++c)
                acc[c] = ffma2(vb[c + q], w2, acc[c]);
        }
        // shift in row orow + p + 2 for the next p
        if (p < KH - 1) {
            const float* rn = sx + (orow + p + 2) * PITCH + ocol;
            #pragma unroll
            for (int c = 0; c < 32; c += 4) {
                float4 v = *reinterpret_cast<const float4*>(rn + c);
                vb[c+0] = shift_in(vb[c+0], v.x);
                vb[c+1] = shift_in(vb[c+1], v.y);
                vb[c+2] = shift_in(vb[c+2], v.z);
                vb[c+3] = shift_in(vb[c+3], v.w);
            }
        }
    }

    // ---- transpose through shared, then coalesced store ----
    const float b = bias[0];
    __syncthreads();                       // all reads of sx done
    float* tb = sx;                        // reuse as 64 x TPITCH buffer (33 KB)

    #pragma unroll
    for (int c = 0; c < 16; ++c) {
        tb[orow * TPITCH + ocol + c]       = f2_lo(acc[c]) + b;
        tb[(orow + 1) * TPITCH + ocol + c] = f2_hi(acc[c]) + b;
    }
    __syncthreads();

    #pragma unroll
    for (int k = 0; k < 32; ++k) {
        const int idx = tid + k * 256;     // 0 .. 8191
        const int r = idx >> 7;            // 0..63
        const int c = idx & 127;           // 0..127
        const int gr = row0 + r;
        const int gc = col0 + c;
        if (gr < OUT_H && gc < OUT_W)
            out[(size_t)gr * OUT_W + gc] = tb[r * TPITCH + c];
    }
}

extern "C" void kernel_launch(void* const* d_in, const int* in_sizes, int n_in,
                              void* d_out, int out_size)
{
    (void)in_sizes; (void)n_in; (void)out_size;
    const float* x    = (const float*)d_in[0];
    const float* w    = (const float*)d_in[1];
    const float* bias = (const float*)d_in[2];
    float* out        = (float*)d_out;

    dim3 grid((OUT_W + TILE_COLS - 1) / TILE_COLS,   // 32
              (OUT_H + TILE_ROWS - 1) / TILE_ROWS);  // 64
    conv2d_f32x2_kernel<<<grid, 256>>>(x, w, bias, out);
}

// round 10
// speedup vs baseline: 1.2584x; 1.2584x over previous
#include <cuda_runtime.h>
#include <cuda_fp16.h>
#include <cstdint>

typedef unsigned int u32;

#define IN_DIM   4096
#define OUT_DIM  4081
#define TILE_R   64
#define TILE_C   128
#define NTILES   2048          // 64 x 32 tiles
#define XT_ROWS  80            // 64 + 16 halo
#define XT_STRIDE 304          // bytes per x-tile row (152 halves)
#define NCHUNK   72            // 24 p * 3 q-octets

// all shifted-weight copies, fp16 hi plane: [chunk][m=64][k8] (16B per m-row)
__device__ __half g_A[NCHUNK * 64 * 8];

// smem layout (dynamic)
#define S_A        0
#define SZ_A       (NCHUNK * 1024)          // 73728
#define S_XH       SZ_A
#define SZ_X       (XT_ROWS * XT_STRIDE)    // 24320
#define S_XL       (S_XH + SZ_X)
#define SMEM_TOTAL (S_XL + SZ_X)            // 122368
#define S_D        S_XH                     // epilogue reuses x region
#define D_STRIDE   132                      // floats

__device__ __forceinline__ u32 smem_u32(const void* p) {
    u32 a;
    asm("{ .reg .u64 t; cvta.to.shared.u64 t, %1; cvt.u32.u64 %0, t; }" : "=r"(a) : "l"(p));
    return a;
}

#define LDSM4(r, a) \
    asm volatile("ldmatrix.sync.aligned.m8n8.x4.shared.b16 {%0,%1,%2,%3}, [%4];" \
        : "=r"((r)[0]), "=r"((r)[1]), "=r"((r)[2]), "=r"((r)[3]) : "r"(a))

#define MMA8(d, a0, a1, b) \
    asm volatile("mma.sync.aligned.m16n8k8.row.col.f32.f16.f16.f32 " \
        "{%0,%1,%2,%3}, {%4,%5}, {%6}, {%0,%1,%2,%3};" \
        : "+f"((d)[0]), "+f"((d)[1]), "+f"((d)[2]), "+f"((d)[3]) \
        : "r"(a0), "r"(a1), "r"(b))

// ============ prep: build shifted-weight matrix A (w_hi) ============
// A[c=(p,t)][m=(di,dj)][kk] = w[p-di][ (8t+kk) - dj ]  (0 outside [0,16)^2)
__global__ void prep_a_kernel(const float* __restrict__ w) {
    int e  = blockIdx.x * 256 + threadIdx.x;   // [0, 36864)
    int c  = e >> 9;
    int m  = (e >> 3) & 63;
    int kk = e & 7;
    int p  = c / 3;
    int t  = c - p * 3;
    int q  = t * 8 + kk;
    int di = m >> 3, dj = m & 7;
    int pi = p - di, qi = q - dj;
    float v = (pi >= 0 && pi < 16 && qi >= 0 && qi < 16) ? w[pi * 16 + qi] : 0.0f;
    g_A[e] = __float2half(v);
}

// ============ main: persistent implicit-GEMM conv ============
__global__ __launch_bounds__(256, 1)
void conv_hmma_kernel(const float* __restrict__ x,
                      const float* __restrict__ bias,
                      float* __restrict__ out)
{
    extern __shared__ char sm[];
    const u32 smb  = smem_u32(sm);
    const int tid  = threadIdx.x;
    const int lane = tid & 31;
    const int wid  = tid >> 5;
    const int wm   = wid >> 2;      // 0..1  (M half)
    const int wn   = wid & 3;       // 0..3  (N quarter)
    const float bv = bias[0];

    // ---- stage A once per CTA lifetime (72 KB, L2-resident source) ----
    {
        const uint4* src = reinterpret_cast<const uint4*>(g_A);
        uint4* dst = reinterpret_cast<uint4*>(sm + S_A);
        for (int u = tid; u < SZ_A / 16; u += 256) dst[u] = src[u];
    }

    // ldmatrix lane bases
    const u32 aBase = smb + S_A + (u32)((wm * 32 + lane) * 16);
    const int nl = wn * 32 + lane;          // this lane's n for B tiles
    const int bi = nl >> 4, bj = nl & 15;
    const u32 bOffLane = (u32)(bi * 8 * XT_STRIDE + bj * 16);
    const int g_  = lane >> 2;              // mma group id
    const int tig = lane & 3;

    __syncthreads();

    for (int tile = blockIdx.x; tile < NTILES; tile += gridDim.x) {
        const int i0 = (tile >> 5) * TILE_R;
        const int j0 = (tile & 31) * TILE_C;

        // ---- stage x tile: fp32 -> (hi, lo) fp16 planes ----
        for (int u = tid; u < XT_ROWS * 38; u += 256) {
            const int r  = u / 38;
            const int c4 = u - r * 38;
            const int gr = i0 + r, gc = j0 + c4 * 4;
            float4 v = make_float4(0.f, 0.f, 0.f, 0.f);
            if (gr < IN_DIM && gc < IN_DIM)      // gc is 4-aligned; 4096 % 4 == 0
                v = *reinterpret_cast<const float4*>(x + (size_t)gr * IN_DIM + gc);
            __half hx = __float2half(v.x), hy = __float2half(v.y),
                   hz = __float2half(v.z), hw = __float2half(v.w);
            __half lx = __float2half(v.x - __half2float(hx));
            __half ly = __float2half(v.y - __half2float(hy));
            __half lz = __float2half(v.z - __half2float(hz));
            __half lw = __float2half(v.w - __half2float(hw));
            uint2 hp, lp;
            hp.x = (u32)__half_as_ushort(hx) | ((u32)__half_as_ushort(hy) << 16);
            hp.y = (u32)__half_as_ushort(hz) | ((u32)__half_as_ushort(hw) << 16);
            lp.x = (u32)__half_as_ushort(lx) | ((u32)__half_as_ushort(ly) << 16);
            lp.y = (u32)__half_as_ushort(lz) | ((u32)__half_as_ushort(lw) << 16);
            *reinterpret_cast<uint2*>(sm + S_XH + r * XT_STRIDE + c4 * 8) = hp;
            *reinterpret_cast<uint2*>(sm + S_XL + r * XT_STRIDE + c4 * 8) = lp;
        }
        __syncthreads();

        // ---- mainloop: 24 p x 3 q-octets; fused hi+lo passes share A frags ----
        float acc[2][4][4];
        #pragma unroll
        for (int a = 0; a < 2; ++a)
            #pragma unroll
            for (int b = 0; b < 4; ++b)
                #pragma unroll
                for (int i = 0; i < 4; ++i) acc[a][b][i] = 0.f;

        const u32 bhBase = smb + S_XH + bOffLane;
        const u32 blBase = smb + S_XL + bOffLane;

        for (int p = 0; p < 24; ++p) {
            const u32 aP = aBase + (u32)(p * 3072);
            const u32 bP = (u32)(p * XT_STRIDE);
            #pragma unroll
            for (int t = 0; t < 3; ++t) {
                u32 aR[4], bh[4], bl[4];
                LDSM4(aR, aP + t * 1024);
                LDSM4(bh, bhBase + bP + t * 16);
                LDSM4(bl, blBase + bP + t * 16);
                #pragma unroll
                for (int mt = 0; mt < 2; ++mt)
                    #pragma unroll
                    for (int nt = 0; nt < 4; ++nt) {
                        MMA8(acc[mt][nt], aR[2 * mt], aR[2 * mt + 1], bh[nt]);
                        MMA8(acc[mt][nt], aR[2 * mt], aR[2 * mt + 1], bl[nt]);
                    }
            }
        }

        // ---- epilogue: scatter frags -> smem D (output layout), coalesced out ----
        __syncthreads();          // x planes dead; reuse as D
        float* sD = reinterpret_cast<float*>(sm + S_D);
        #pragma unroll
        for (int mt = 0; mt < 2; ++mt)
            #pragma unroll
            for (int nt = 0; nt < 4; ++nt)
                #pragma unroll
                for (int i = 0; i < 4; ++i) {
                    const int m = wm * 32 + mt * 16 + g_ + ((i >> 1) ? 8 : 0);
                    const int n = wn * 32 + nt * 8 + tig * 2 + (i & 1);
                    const int rl = ((n >> 4) << 3) + (m >> 3);   // 8*bi + di
                    const int cl = ((n & 15) << 3) + (m & 7);    // 8*bj + dj
                    sD[rl * D_STRIDE + cl] = acc[mt][nt][i] + bv;
                }
        __syncthreads();

        for (int u = tid; u < 64 * 32; u += 256) {
            const int r = u >> 5, c4 = (u & 31) * 4;
            const int gr = i0 + r, gc0 = j0 + c4;
            if (gr < OUT_DIM) {
                float* op = out + (size_t)gr * OUT_DIM;
                const float* sp = sD + r * D_STRIDE + c4;
                #pragma unroll
                for (int k = 0; k < 4; ++k)
                    if (gc0 + k < OUT_DIM) op[gc0 + k] = sp[k];
            }
        }
        __syncthreads();          // protect S_D before next tile restages x
    }
}

// ============ launch ============
extern "C" void kernel_launch(void* const* d_in, const int* in_sizes, int n_in,
                              void* d_out, int out_size)
{
    (void)in_sizes; (void)n_in; (void)out_size;
    const float* x    = (const float*)d_in[0];
    const float* w    = (const float*)d_in[1];
    const float* bias = (const float*)d_in[2];
    float* out        = (float*)d_out;

    cudaFuncSetAttribute(conv_hmma_kernel,
                         cudaFuncAttributeMaxDynamicSharedMemorySize, SMEM_TOTAL);

    prep_a_kernel<<<144, 256>>>(w);                       // 36864 elems
    conv_hmma_kernel<<<152, 256, SMEM_TOTAL>>>(x, bias, out);
}

// round 12
// speedup vs baseline: 2.4390x; 1.9381x over previous
#include <cuda_runtime.h>
#include <cuda_fp16.h>
#include <cstdint>

typedef unsigned int u32;

#define IN_DIM   4096
#define OUT_DIM  4081
#define TILE_R   64
#define TILE_C   128
#define NTILES   2048          // 64 x 32 tiles
#define XT_ROWS  80            // 64 + 16 halo
#define XT_STRIDE 304          // bytes per x-tile row (152 halves)
#define NCHUNK   72            // 24 p * 3 q-octets

// shifted-weight copies, fp16: [chunk][m=64][k8] (16B per m-row)
__device__ __half g_A[NCHUNK * 64 * 8];

// smem layout (dynamic)
#define S_A        0
#define SZ_A       (NCHUNK * 1024)          // 73728
#define S_XH       SZ_A
#define SZ_X       (XT_ROWS * XT_STRIDE)    // 24320
#define S_D        S_XH                     // epilogue reuses x region
#define D_STRIDE   132                      // floats; 64*132*4 = 33792
#define SMEM_TOTAL (SZ_A + 33792)           // 107520 (105 KB) -> 2 CTAs/SM

__device__ __forceinline__ u32 smem_u32(const void* p) {
    u32 a;
    asm("{ .reg .u64 t; cvta.to.shared.u64 t, %1; cvt.u32.u64 %0, t; }" : "=r"(a) : "l"(p));
    return a;
}

#define LDSM4(r, a) \
    asm volatile("ldmatrix.sync.aligned.m8n8.x4.shared.b16 {%0,%1,%2,%3}, [%4];" \
        : "=r"((r)[0]), "=r"((r)[1]), "=r"((r)[2]), "=r"((r)[3]) : "r"(a))

#define MMA8(d, a0, a1, b) \
    asm volatile("mma.sync.aligned.m16n8k8.row.col.f32.f16.f16.f32 " \
        "{%0,%1,%2,%3}, {%4,%5}, {%6}, {%0,%1,%2,%3};" \
        : "+f"((d)[0]), "+f"((d)[1]), "+f"((d)[2]), "+f"((d)[3]) \
        : "r"(a0), "r"(a1), "r"(b))

// ============ prep: build shifted-weight matrix A ============
// A[c=(p,t)][m=(di,dj)][kk] = w[p-di][(8t+kk)-dj]  (0 outside [0,16)^2)
__global__ void prep_a_kernel(const float* __restrict__ w) {
    int e  = blockIdx.x * 256 + threadIdx.x;   // [0, 36864)
    int c  = e >> 9;
    int m  = (e >> 3) & 63;
    int kk = e & 7;
    int p  = c / 3;
    int t  = c - p * 3;
    int q  = t * 8 + kk;
    int di = m >> 3, dj = m & 7;
    int pi = p - di, qi = q - dj;
    float v = (pi >= 0 && pi < 16 && qi >= 0 && qi < 16) ? w[pi * 16 + qi] : 0.0f;
    g_A[e] = __float2half(v);
}

// ============ main: persistent implicit-GEMM conv ============
__global__ __launch_bounds__(256, 2)
void conv_hmma_kernel(const float* __restrict__ x,
                      const float* __restrict__ bias,
                      float* __restrict__ out)
{
    extern __shared__ char sm[];
    const u32 smb  = smem_u32(sm);
    const int tid  = threadIdx.x;
    const int lane = tid & 31;
    const int wid  = tid >> 5;
    const int wm   = wid >> 2;      // 0..1  (M half)
    const int wn   = wid & 3;       // 0..3  (N quarter)
    const float bv = bias[0];

    // ---- stage A once per CTA lifetime (72 KB; L2-resident source) ----
    {
        const uint4* src = reinterpret_cast<const uint4*>(g_A);
        uint4* dst = reinterpret_cast<uint4*>(sm + S_A);
        for (int u = tid; u < SZ_A / 16; u += 256) dst[u] = src[u];
    }

    // ldmatrix lane bases
    const u32 aBase = smb + S_A + (u32)((wm * 32 + lane) * 16);
    const int nl = wn * 32 + lane;          // this lane's n for B tiles
    const int bi = nl >> 4, bj = nl & 15;
    const u32 bBase = smb + S_XH + (u32)(bi * 8 * XT_STRIDE + bj * 16);
    const int g_  = lane >> 2;              // mma group id
    const int tig = lane & 3;

    __syncthreads();

    for (int tile = blockIdx.x; tile < NTILES; tile += gridDim.x) {
        const int i0 = (tile >> 5) * TILE_R;
        const int j0 = (tile & 31) * TILE_C;

        // ---- stage x tile: fp32 -> fp16 (single plane) ----
        for (int u = tid; u < XT_ROWS * 38; u += 256) {
            const int r  = u / 38;
            const int c4 = u - r * 38;
            const int gr = i0 + r, gc = j0 + c4 * 4;
            float4 v = make_float4(0.f, 0.f, 0.f, 0.f);
            if (gr < IN_DIM && gc < IN_DIM)      // gc 4-aligned, IN_DIM % 4 == 0
                v = *reinterpret_cast<const float4*>(x + (size_t)gr * IN_DIM + gc);
            uint2 hp;
            hp.x = (u32)__half_as_ushort(__float2half(v.x))
                 | ((u32)__half_as_ushort(__float2half(v.y)) << 16);
            hp.y = (u32)__half_as_ushort(__float2half(v.z))
                 | ((u32)__half_as_ushort(__float2half(v.w)) << 16);
            *reinterpret_cast<uint2*>(sm + S_XH + r * XT_STRIDE + c4 * 8) = hp;
        }
        __syncthreads();

        // ---- pipelined mainloop over 72 chunks ----
        float acc[2][4][4];
        #pragma unroll
        for (int a = 0; a < 2; ++a)
            #pragma unroll
            for (int b = 0; b < 4; ++b)
                #pragma unroll
                for (int i = 0; i < 4; ++i) acc[a][b][i] = 0.f;

        u32 aF[2][4], bF[2][4];
        u32 aAddr = aBase;
        u32 bAddr = bBase;
        LDSM4(aF[0], aAddr);
        LDSM4(bF[0], bAddr);

        #pragma unroll 6
        for (int c = 0; c < NCHUNK; ++c) {
            const int cur = c & 1, nxt = cur ^ 1;
            const u32 aN = aAddr + 1024;
            const u32 bN = bAddr + ((c % 3 == 2) ? 272u : 16u);  // 272 = 304-32
            if (c < NCHUNK - 1) {
                LDSM4(aF[nxt], aN);
                LDSM4(bF[nxt], bN);
            }
            #pragma unroll
            for (int mt = 0; mt < 2; ++mt)
                #pragma unroll
                for (int nt = 0; nt < 4; ++nt)
                    MMA8(acc[mt][nt], aF[cur][2 * mt], aF[cur][2 * mt + 1], bF[cur][nt]);
            aAddr = aN;
            bAddr = bN;
        }

        // ---- epilogue: frags -> smem D (output layout) -> coalesced out ----
        __syncthreads();          // x plane dead; reuse as D
        float* sD = reinterpret_cast<float*>(sm + S_D);
        #pragma unroll
        for (int mt = 0; mt < 2; ++mt)
            #pragma unroll
            for (int nt = 0; nt < 4; ++nt)
                #pragma unroll
                for (int i = 0; i < 4; ++i) {
                    const int m = wm * 32 + mt * 16 + g_ + ((i >> 1) ? 8 : 0);
                    const int n = wn * 32 + nt * 8 + tig * 2 + (i & 1);
                    const int rl = ((n >> 4) << 3) + (m >> 3);   // 8*bi + di
                    const int cl = ((n & 15) << 3) + (m & 7);    // 8*bj + dj
                    sD[rl * D_STRIDE + cl] = acc[mt][nt][i] + bv;
                }
        __syncthreads();

        for (int u = tid; u < 64 * 32; u += 256) {
            const int r = u >> 5, c4 = (u & 31) * 4;
            const int gr = i0 + r, gc0 = j0 + c4;
            if (gr < OUT_DIM) {
                float* op = out + (size_t)gr * OUT_DIM;
                const float* sp = sD + r * D_STRIDE + c4;
                #pragma unroll
                for (int k = 0; k < 4; ++k)
                    if (gc0 + k < OUT_DIM) op[gc0 + k] = sp[k];
            }
        }
        __syncthreads();          // protect S_D before next tile restages x
    }
}

// ============ launch ============
extern "C" void kernel_launch(void* const* d_in, const int* in_sizes, int n_in,
                              void* d_out, int out_size)
{
    (void)in_sizes; (void)n_in; (void)out_size;
    const float* x    = (const float*)d_in[0];
    const float* w    = (const float*)d_in[1];
    const float* bias = (const float*)d_in[2];
    float* out        = (float*)d_out;

    cudaFuncSetAttribute(conv_hmma_kernel,
                         cudaFuncAttributeMaxDynamicSharedMemorySize, SMEM_TOTAL);

    prep_a_kernel<<<144, 256>>>(w);                       // 36864 elems
    conv_hmma_kernel<<<304, 256, SMEM_TOTAL>>>(x, bias, out);
}